// round 11
// baseline (speedup 1.0000x reference)
#include <cuda_runtime.h>
#include <cuda_bf16.h>
#include <cuda_fp16.h>
#include <cstdint>

// Problem constants (fixed by dataset): N=100000, D=64, E=1600000
#define NMAX 100000
#define EMAX 1600000
#define ESLOTS (EMAX + NMAX)   // rowptr built from deg upper-bounds counts
#define F    192               // 3*D features per hop stage
#define OUTC 576               // 9*64 output columns per node
#define SCAN_CHUNK 4096        // elems per scan block (1024 thr x 4)
#define MAXBLK 64

// ---- scratch (static device globals; no runtime allocation allowed) ----
__device__ __half  g_xh [(size_t)NMAX * 64];  // x in fp16 (hop-1 gather)
__device__ __half  g_y1h[(size_t)NMAX * F];   // hop-1 result, fp16
__device__ float2  g_s2[NMAX];                // (rsqrt(deg), sqrt(deg)) fp32
__device__ __half2 g_s2h[NMAX];               // (rsqrt(deg), sqrt(deg)) fp16
__device__ int   g_rowptr[NMAX + 1];
__device__ int   g_cursor[NMAX];              // fill cursor; after fill = row end
__device__ int   g_bsum[MAXBLK];              // scan block partials
__device__ int   g_ecol[ESLOTS];              // CSR column indices

// ---------------------------------------------------------------------------
// K1: per-node scale factors (fp32 + fp16) + x -> fp16 conversion
// ---------------------------------------------------------------------------
__global__ void init_kernel(const float* __restrict__ x,
                            const float* __restrict__ deg, int N) {
    int t = blockIdx.x * blockDim.x + threadIdx.x;
    int total = N * 32;                 // N*64 floats as float2
    if (t < total) {
        float2 v = __ldg(((const float2*)x) + t);
        ((__half2*)g_xh)[t] = __floats2half2_rn(v.x, v.y);
    }
    if (t < N) {
        float d = __ldg(&deg[t]);
        float r = rsqrtf(d);
        float q = d * r;
        g_s2[t]  = make_float2(r, q);
        g_s2h[t] = __floats2half2_rn(r, q);
    }
}

// ---------------------------------------------------------------------------
// scanA: per-block local exclusive scan of (int)deg + block partial.
// scanC: warp 0 sums predecessors' partials (visibility guaranteed by the
//        kernel boundary), then all threads add the offset and init cursor.
// ---------------------------------------------------------------------------
__global__ void scanA_kernel(const float* __restrict__ deg, int N) {
    __shared__ int warp_sums[32];
    const int tid = threadIdx.x, lane = tid & 31, wid = tid >> 5;
    int idx = blockIdx.x * SCAN_CHUNK + tid * 4;

    int v0 = (idx     < N) ? (int)__ldg(&deg[idx])     : 0;
    int v1 = (idx + 1 < N) ? (int)__ldg(&deg[idx + 1]) : 0;
    int v2 = (idx + 2 < N) ? (int)__ldg(&deg[idx + 2]) : 0;
    int v3 = (idx + 3 < N) ? (int)__ldg(&deg[idx + 3]) : 0;
    int t = v0 + v1 + v2 + v3;

    int s = t;
    #pragma unroll
    for (int off = 1; off < 32; off <<= 1) {
        int u = __shfl_up_sync(0xFFFFFFFFu, s, off);
        if (lane >= off) s += u;
    }
    if (lane == 31) warp_sums[wid] = s;
    __syncthreads();
    if (wid == 0) {
        int ws = warp_sums[lane];
        int s2 = ws;
        #pragma unroll
        for (int off = 1; off < 32; off <<= 1) {
            int u = __shfl_up_sync(0xFFFFFFFFu, s2, off);
            if (lane >= off) s2 += u;
        }
        warp_sums[lane] = s2 - ws;
    }
    __syncthreads();
    int excl = warp_sums[wid] + (s - t);   // block-local exclusive prefix

    if (idx     < N) g_rowptr[idx]     = excl;
    if (idx + 1 < N) g_rowptr[idx + 1] = excl + v0;
    if (idx + 2 < N) g_rowptr[idx + 2] = excl + v0 + v1;
    if (idx + 3 < N) g_rowptr[idx + 3] = excl + v0 + v1 + v2;
    if (tid == 1023) g_bsum[blockIdx.x] = excl + t;   // block total
}

__global__ void scanC_kernel(int N) {
    __shared__ int s_off;
    const int tid = threadIdx.x, lane = tid & 31;
    if (tid < 32) {                         // warp 0 sums predecessor partials
        int part = (lane < blockIdx.x) ? __ldg(&g_bsum[lane]) : 0;
        #pragma unroll
        for (int off = 16; off > 0; off >>= 1)
            part += __shfl_down_sync(0xFFFFFFFFu, part, off);
        if (lane == 0) s_off = part;
    }
    __syncthreads();
    int off = s_off;
    int idx = blockIdx.x * SCAN_CHUNK + tid * 4;
    #pragma unroll
    for (int k = 0; k < 4; k++) {
        if (idx + k < N) {
            int r = g_rowptr[idx + k] + off;
            g_rowptr[idx + k] = r;
            g_cursor[idx + k] = r;
        }
    }
}

// ---------------------------------------------------------------------------
// K3: scatter edges into CSR buckets, 4 edges/thread for MLP
// ---------------------------------------------------------------------------
__global__ void fill_kernel(const int* __restrict__ row, const int* __restrict__ col, int E) {
    int t = blockIdx.x * blockDim.x + threadIdx.x;
    int e = t * 4;
    if (e + 3 < E) {
        int4 r4 = __ldg((const int4*)(row + e));
        int4 c4 = __ldg((const int4*)(col + e));
        int p0 = atomicAdd(&g_cursor[r4.x], 1);
        int p1 = atomicAdd(&g_cursor[r4.y], 1);
        int p2 = atomicAdd(&g_cursor[r4.z], 1);
        int p3 = atomicAdd(&g_cursor[r4.w], 1);
        g_ecol[p0] = c4.x; g_ecol[p1] = c4.y;
        g_ecol[p2] = c4.z; g_ecol[p3] = c4.w;
    } else {
        for (; e < E; e++) {
            int p = atomicAdd(&g_cursor[row[e]], 1);
            g_ecol[p] = col[e];
        }
    }
}

// ---------------------------------------------------------------------------
// K4: hop-1 SpMM, fp16 HFMA2 accumulation. Warp per node; lane l owns half2
//     column l of each of the 3 feature groups (offsets 0/32/64 half2 units).
// ---------------------------------------------------------------------------
__global__ void spmm1_kernel(const float* __restrict__ deg, int N) {
    int w = (blockIdx.x * blockDim.x + threadIdx.x) >> 5;
    int lane = threadIdx.x & 31;
    if (w >= N) return;
    int s = g_rowptr[w], e = g_cursor[w];   // true end after fill

    __half2 a0 = __float2half2_rn(0.f);
    __half2 a1 = a0, a2 = a0;
    #pragma unroll 4
    for (int p = s; p < e; p++) {
        int j = __ldg(&g_ecol[p]);
        __half2 xv = __ldg(((const __half2*)(g_xh + (size_t)j * 64)) + lane);
        __half2 sh = __ldg(&g_s2h[j]);        // uniform broadcast
        __half2 rr = __low2half2(sh);
        __half2 qq = __high2half2(sh);
        a0 = __hadd2(a0, xv);
        a1 = __hfma2(xv, rr, a1);
        a2 = __hfma2(xv, qq, a2);
    }
    float dr = 1.0f / deg[w];
    float2 f0 = __half22float2(a0);
    float2 f1 = __half22float2(a1);
    float2 f2 = __half22float2(a2);
    __half2* outh = (__half2*)(g_y1h + (size_t)w * F);
    outh[lane]      = __floats2half2_rn(f0.x * dr, f0.y * dr);
    outh[lane + 32] = __floats2half2_rn(f1.x * dr, f1.y * dr);
    outh[lane + 64] = __floats2half2_rn(f2.x * dr, f2.y * dr);
}

// ---------------------------------------------------------------------------
// K5: FUSED hop-2 SpMM + transposed output.
//     Gather: lane l<24 loads uint4 (16B) chunk l of the 384B y1 row ->
//     ONE LDG.128 + 4 HADD2 per edge. Output stores use __stcs (evict-first)
//     so the 230MB write-once stream doesn't evict the L2-resident y1.
// ---------------------------------------------------------------------------
__global__ void spmm2_out_kernel(const float* __restrict__ x,
                                 const float* __restrict__ deg,
                                 float* __restrict__ out, int N) {
    __shared__ float tile[8 * 9 * 65];        // per-warp 585-float tile
    int wid = threadIdx.x >> 5, lane = threadIdx.x & 31;
    int n = blockIdx.x * 8 + wid;
    if (n >= N) return;
    float* t = tile + wid * 585;
    bool act = lane < 24;

    int s = g_rowptr[n], e = g_cursor[n];
    __half2 acc0 = __float2half2_rn(0.f);
    __half2 acc1 = acc0, acc2 = acc0, acc3 = acc0;
    #pragma unroll 4
    for (int p = s; p < e; p++) {
        int j = __ldg(&g_ecol[p]);
        if (act) {
            uint4 v = __ldg(((const uint4*)(g_y1h + (size_t)j * F)) + lane);
            acc0 = __hadd2(acc0, *(__half2*)&v.x);
            acc1 = __hadd2(acc1, *(__half2*)&v.y);
            acc2 = __hadd2(acc2, *(__half2*)&v.z);
            acc3 = __hadd2(acc3, *(__half2*)&v.w);
        }
    }

    float dr = 1.0f / deg[n];
    float2 sc = g_s2[n];
    if (act) {
        int k = lane >> 3, d0 = (lane & 7) * 8;
        float f = (k == 0) ? 1.0f : ((k == 1) ? sc.x : sc.y);

        // own x slice (exact fp32): 8 floats
        const float* xr = x + (size_t)n * 64 + d0;
        float4 xa = __ldg((const float4*)xr);
        float4 xb = __ldg((const float4*)(xr + 4));

        // own y1 slice (same uint4 mapping)
        uint4 yv = __ldg(((const uint4*)(g_y1h + (size_t)n * F)) + lane);
        float2 y0 = __half22float2(*(__half2*)&yv.x);
        float2 y1 = __half22float2(*(__half2*)&yv.y);
        float2 y2 = __half22float2(*(__half2*)&yv.z);
        float2 y3 = __half22float2(*(__half2*)&yv.w);

        float2 a0 = __half22float2(acc0);
        float2 a1 = __half22float2(acc1);
        float2 a2 = __half22float2(acc2);
        float2 a3 = __half22float2(acc3);

        float x0 = xa.x * f, x1 = xa.y * f, x2 = xa.z * f, x3v = xa.w * f;
        float x4 = xb.x * f, x5 = xb.y * f, x6 = xb.z * f, x7 = xb.w * f;

        float* tk = t + k * 65 + d0;               // x3 block
        tk[0] = x0; tk[1] = x1; tk[2] = x2; tk[3] = x3v;
        tk[4] = x4; tk[5] = x5; tk[6] = x6; tk[7] = x7;

        float* t3 = t + (k + 3) * 65 + d0;         // y1 block
        t3[0] = y0.x; t3[1] = y0.y; t3[2] = y1.x; t3[3] = y1.y;
        t3[4] = y2.x; t3[5] = y2.y; t3[6] = y3.x; t3[7] = y3.y;

        float* t6 = t + (k + 6) * 65 + d0;         // y2 = dr*sum - x3
        t6[0] = a0.x * dr - x0; t6[1] = a0.y * dr - x1;
        t6[2] = a1.x * dr - x2; t6[3] = a1.y * dr - x3v;
        t6[4] = a2.x * dr - x4; t6[5] = a2.y * dr - x5;
        t6[6] = a3.x * dr - x6; t6[7] = a3.y * dr - x7;
    }
    __syncwarp();

    // coalesced, L2-evict-first store of the transposed row: out[n, d*9+k]
    float* o = out + (size_t)n * OUTC;
    #pragma unroll
    for (int i = 0; i < 18; i++) {
        int r = i * 32 + lane;
        int d = r / 9, k = r - d * 9;
        __stcs(&o[r], t[k * 65 + d]);
    }
}

// ---------------------------------------------------------------------------
extern "C" void kernel_launch(void* const* d_in, const int* in_sizes, int n_in,
                              void* d_out, int out_size) {
    const float* x   = (const float*)d_in[0];
    const float* deg = (const float*)d_in[1];
    const int*   row = (const int*)d_in[2];
    const int*   col = (const int*)d_in[3];
    float* out = (float*)d_out;

    int N = in_sizes[1];          // deg has N elements
    int E = in_sizes[2];          // row has E elements
    int nblk = (N + SCAN_CHUNK - 1) / SCAN_CHUNK;   // 25 for N=100000

    init_kernel<<<((size_t)N * 32 + 255) / 256, 256>>>(x, deg, N);
    scanA_kernel<<<nblk, 1024>>>(deg, N);
    scanC_kernel<<<nblk, 1024>>>(N);
    fill_kernel<<<(E / 4 + 255) / 256, 256>>>(row, col, E);
    spmm1_kernel<<<((size_t)N * 32 + 255) / 256, 256>>>(deg, N);
    spmm2_out_kernel<<<(N + 7) / 8, 256>>>(x, deg, out, N);
}

// round 12
// speedup vs baseline: 1.4250x; 1.4250x over previous
#include <cuda_runtime.h>
#include <cuda_bf16.h>
#include <cuda_fp16.h>
#include <cstdint>

// Problem constants (fixed by dataset): N=100000, D=64, E=1600000
#define NMAX 100000
#define EMAX 1600000
#define ESLOTS (EMAX + NMAX)   // rowptr built from deg upper-bounds counts
#define F    192               // 3*D features per hop stage
#define OUTC 576               // 9*64 output columns per node
#define SCAN_CHUNK 4096        // elems per scan block (1024 thr x 4)
#define MAXBLK 64

// ---- scratch (static device globals; no runtime allocation allowed) ----
__device__ __half  g_xh [(size_t)NMAX * 64];  // x in fp16 (hop-1 gather)
__device__ __half  g_y1h[(size_t)NMAX * F];   // hop-1 result, fp16
__device__ float2  g_s2[NMAX];                // (rsqrt(deg), sqrt(deg)) fp32
__device__ __half2 g_s2h[NMAX];               // (rsqrt(deg), sqrt(deg)) fp16
__device__ int   g_rowptr[NMAX + 1];
__device__ int   g_cursor[NMAX];              // fill cursor; after fill = row end
__device__ int   g_bsum[MAXBLK];              // scan block partials
__device__ int   g_ecol[ESLOTS];              // CSR column indices

// ---------------------------------------------------------------------------
// K1: per-node scale factors (fp32 + fp16) + x -> fp16 conversion
// ---------------------------------------------------------------------------
__global__ void init_kernel(const float* __restrict__ x,
                            const float* __restrict__ deg, int N) {
    int t = blockIdx.x * blockDim.x + threadIdx.x;
    int total = N * 32;                 // N*64 floats as float2
    if (t < total) {
        float2 v = __ldg(((const float2*)x) + t);
        ((__half2*)g_xh)[t] = __floats2half2_rn(v.x, v.y);
    }
    if (t < N) {
        float d = __ldg(&deg[t]);
        float r = rsqrtf(d);
        float q = d * r;
        g_s2[t]  = make_float2(r, q);
        g_s2h[t] = __floats2half2_rn(r, q);
    }
}

// ---------------------------------------------------------------------------
// scanA: per-block local exclusive scan of (int)deg + block partial.
// scanC: warp 0 sums predecessors' partials (kernel boundary guarantees
//        visibility), then all threads add the offset and init cursor.
// ---------------------------------------------------------------------------
__global__ void scanA_kernel(const float* __restrict__ deg, int N) {
    __shared__ int warp_sums[32];
    const int tid = threadIdx.x, lane = tid & 31, wid = tid >> 5;
    int idx = blockIdx.x * SCAN_CHUNK + tid * 4;

    int v0 = (idx     < N) ? (int)__ldg(&deg[idx])     : 0;
    int v1 = (idx + 1 < N) ? (int)__ldg(&deg[idx + 1]) : 0;
    int v2 = (idx + 2 < N) ? (int)__ldg(&deg[idx + 2]) : 0;
    int v3 = (idx + 3 < N) ? (int)__ldg(&deg[idx + 3]) : 0;
    int t = v0 + v1 + v2 + v3;

    int s = t;
    #pragma unroll
    for (int off = 1; off < 32; off <<= 1) {
        int u = __shfl_up_sync(0xFFFFFFFFu, s, off);
        if (lane >= off) s += u;
    }
    if (lane == 31) warp_sums[wid] = s;
    __syncthreads();
    if (wid == 0) {
        int ws = warp_sums[lane];
        int s2 = ws;
        #pragma unroll
        for (int off = 1; off < 32; off <<= 1) {
            int u = __shfl_up_sync(0xFFFFFFFFu, s2, off);
            if (lane >= off) s2 += u;
        }
        warp_sums[lane] = s2 - ws;
    }
    __syncthreads();
    int excl = warp_sums[wid] + (s - t);   // block-local exclusive prefix

    if (idx     < N) g_rowptr[idx]     = excl;
    if (idx + 1 < N) g_rowptr[idx + 1] = excl + v0;
    if (idx + 2 < N) g_rowptr[idx + 2] = excl + v0 + v1;
    if (idx + 3 < N) g_rowptr[idx + 3] = excl + v0 + v1 + v2;
    if (tid == 1023) g_bsum[blockIdx.x] = excl + t;   // block total
}

__global__ void scanC_kernel(int N) {
    __shared__ int s_off;
    const int tid = threadIdx.x, lane = tid & 31;
    if (tid < 32) {                         // warp 0 sums predecessor partials
        int part = (lane < blockIdx.x) ? __ldg(&g_bsum[lane]) : 0;
        #pragma unroll
        for (int off = 16; off > 0; off >>= 1)
            part += __shfl_down_sync(0xFFFFFFFFu, part, off);
        if (lane == 0) s_off = part;
    }
    __syncthreads();
    int off = s_off;
    int idx = blockIdx.x * SCAN_CHUNK + tid * 4;
    #pragma unroll
    for (int k = 0; k < 4; k++) {
        if (idx + k < N) {
            int r = g_rowptr[idx + k] + off;
            g_rowptr[idx + k] = r;
            g_cursor[idx + k] = r;
        }
    }
}

// ---------------------------------------------------------------------------
// K3: scatter edges into CSR buckets, 4 edges/thread for MLP
// ---------------------------------------------------------------------------
__global__ void fill_kernel(const int* __restrict__ row, const int* __restrict__ col, int E) {
    int t = blockIdx.x * blockDim.x + threadIdx.x;
    int e = t * 4;
    if (e + 3 < E) {
        int4 r4 = __ldg((const int4*)(row + e));
        int4 c4 = __ldg((const int4*)(col + e));
        int p0 = atomicAdd(&g_cursor[r4.x], 1);
        int p1 = atomicAdd(&g_cursor[r4.y], 1);
        int p2 = atomicAdd(&g_cursor[r4.z], 1);
        int p3 = atomicAdd(&g_cursor[r4.w], 1);
        g_ecol[p0] = c4.x; g_ecol[p1] = c4.y;
        g_ecol[p2] = c4.z; g_ecol[p3] = c4.w;
    } else {
        for (; e < E; e++) {
            int p = atomicAdd(&g_cursor[row[e]], 1);
            g_ecol[p] = col[e];
        }
    }
}

// ---------------------------------------------------------------------------
// K4: hop-1 SpMM, fp16 HFMA2 accumulation. Warp per node; lane l owns half2
//     column l of each of the 3 feature groups (offsets 0/32/64 half2 units).
// ---------------------------------------------------------------------------
__global__ void spmm1_kernel(const float* __restrict__ deg, int N) {
    int w = (blockIdx.x * blockDim.x + threadIdx.x) >> 5;
    int lane = threadIdx.x & 31;
    if (w >= N) return;
    int s = g_rowptr[w], e = g_cursor[w];   // true end after fill

    __half2 a0 = __float2half2_rn(0.f);
    __half2 a1 = a0, a2 = a0;
    #pragma unroll 4
    for (int p = s; p < e; p++) {
        int j = __ldg(&g_ecol[p]);
        __half2 xv = __ldg(((const __half2*)(g_xh + (size_t)j * 64)) + lane);
        __half2 sh = __ldg(&g_s2h[j]);        // uniform broadcast
        __half2 rr = __low2half2(sh);
        __half2 qq = __high2half2(sh);
        a0 = __hadd2(a0, xv);
        a1 = __hfma2(xv, rr, a1);
        a2 = __hfma2(xv, qq, a2);
    }
    float dr = 1.0f / deg[w];
    float2 f0 = __half22float2(a0);
    float2 f1 = __half22float2(a1);
    float2 f2 = __half22float2(a2);
    __half2* outh = (__half2*)(g_y1h + (size_t)w * F);
    outh[lane]      = __floats2half2_rn(f0.x * dr, f0.y * dr);
    outh[lane + 32] = __floats2half2_rn(f1.x * dr, f1.y * dr);
    outh[lane + 64] = __floats2half2_rn(f2.x * dr, f2.y * dr);
}

// ---------------------------------------------------------------------------
// K5: FUSED hop-2 SpMM + transposed output.
//     Gather: lane l<24 loads uint4 (16B) chunk l of the 384B y1 row ->
//     ONE LDG.128 + 4 HADD2 per edge. Lane l owns group k=l>>3, cols
//     d0..d0+7 with d0=(l&7)*8. Epilogue rebuilds x3 (fp32 exact) and y1,
//     writes the 9x64 padded smem tile, then stores transposed (plain STG —
//     .cs store hints measured as a large regression on this chip).
// ---------------------------------------------------------------------------
__global__ void spmm2_out_kernel(const float* __restrict__ x,
                                 const float* __restrict__ deg,
                                 float* __restrict__ out, int N) {
    __shared__ float tile[8 * 9 * 65];        // per-warp 585-float tile
    int wid = threadIdx.x >> 5, lane = threadIdx.x & 31;
    int n = blockIdx.x * 8 + wid;
    if (n >= N) return;
    float* t = tile + wid * 585;
    bool act = lane < 24;

    int s = g_rowptr[n], e = g_cursor[n];
    __half2 acc0 = __float2half2_rn(0.f);
    __half2 acc1 = acc0, acc2 = acc0, acc3 = acc0;
    #pragma unroll 4
    for (int p = s; p < e; p++) {
        int j = __ldg(&g_ecol[p]);
        if (act) {
            uint4 v = __ldg(((const uint4*)(g_y1h + (size_t)j * F)) + lane);
            acc0 = __hadd2(acc0, *(__half2*)&v.x);
            acc1 = __hadd2(acc1, *(__half2*)&v.y);
            acc2 = __hadd2(acc2, *(__half2*)&v.z);
            acc3 = __hadd2(acc3, *(__half2*)&v.w);
        }
    }

    float dr = 1.0f / deg[n];
    float2 sc = g_s2[n];
    if (act) {
        int k = lane >> 3, d0 = (lane & 7) * 8;
        float f = (k == 0) ? 1.0f : ((k == 1) ? sc.x : sc.y);

        // own x slice (exact fp32): 8 floats
        const float* xr = x + (size_t)n * 64 + d0;
        float4 xa = __ldg((const float4*)xr);
        float4 xb = __ldg((const float4*)(xr + 4));

        // own y1 slice (same uint4 mapping)
        uint4 yv = __ldg(((const uint4*)(g_y1h + (size_t)n * F)) + lane);
        float2 y0 = __half22float2(*(__half2*)&yv.x);
        float2 y1 = __half22float2(*(__half2*)&yv.y);
        float2 y2 = __half22float2(*(__half2*)&yv.z);
        float2 y3 = __half22float2(*(__half2*)&yv.w);

        float2 a0 = __half22float2(acc0);
        float2 a1 = __half22float2(acc1);
        float2 a2 = __half22float2(acc2);
        float2 a3 = __half22float2(acc3);

        float x0 = xa.x * f, x1 = xa.y * f, x2 = xa.z * f, x3v = xa.w * f;
        float x4 = xb.x * f, x5 = xb.y * f, x6 = xb.z * f, x7 = xb.w * f;

        float* tk = t + k * 65 + d0;               // x3 block
        tk[0] = x0; tk[1] = x1; tk[2] = x2; tk[3] = x3v;
        tk[4] = x4; tk[5] = x5; tk[6] = x6; tk[7] = x7;

        float* t3 = t + (k + 3) * 65 + d0;         // y1 block
        t3[0] = y0.x; t3[1] = y0.y; t3[2] = y1.x; t3[3] = y1.y;
        t3[4] = y2.x; t3[5] = y2.y; t3[6] = y3.x; t3[7] = y3.y;

        float* t6 = t + (k + 6) * 65 + d0;         // y2 = dr*sum - x3
        t6[0] = a0.x * dr - x0; t6[1] = a0.y * dr - x1;
        t6[2] = a1.x * dr - x2; t6[3] = a1.y * dr - x3v;
        t6[4] = a2.x * dr - x4; t6[5] = a2.y * dr - x5;
        t6[6] = a3.x * dr - x6; t6[7] = a3.y * dr - x7;
    }
    __syncwarp();

    // coalesced store of the transposed row: out[n, d*9+k]
    float* o = out + (size_t)n * OUTC;
    #pragma unroll
    for (int i = 0; i < 18; i++) {
        int r = i * 32 + lane;
        int d = r / 9, k = r - d * 9;
        o[r] = t[k * 65 + d];
    }
}

// ---------------------------------------------------------------------------
extern "C" void kernel_launch(void* const* d_in, const int* in_sizes, int n_in,
                              void* d_out, int out_size) {
    const float* x   = (const float*)d_in[0];
    const float* deg = (const float*)d_in[1];
    const int*   row = (const int*)d_in[2];
    const int*   col = (const int*)d_in[3];
    float* out = (float*)d_out;

    int N = in_sizes[1];          // deg has N elements
    int E = in_sizes[2];          // row has E elements
    int nblk = (N + SCAN_CHUNK - 1) / SCAN_CHUNK;   // 25 for N=100000

    init_kernel<<<((size_t)N * 32 + 255) / 256, 256>>>(x, deg, N);
    scanA_kernel<<<nblk, 1024>>>(deg, N);
    scanC_kernel<<<nblk, 1024>>>(N);
    fill_kernel<<<(E / 4 + 255) / 256, 256>>>(row, col, E);
    spmm1_kernel<<<((size_t)N * 32 + 255) / 256, 256>>>(deg, N);
    spmm2_out_kernel<<<(N + 7) / 8, 256>>>(x, deg, out, N);
}

// round 17
// speedup vs baseline: 1.4900x; 1.0456x over previous
#include <cuda_runtime.h>
#include <cuda_bf16.h>
#include <cuda_fp16.h>
#include <cstdint>

// Problem constants (fixed by dataset): N=100000, D=64, E=1600000
#define NMAX 100000
#define EMAX 1600000
#define ESLOTS (EMAX + NMAX)   // rowptr built from deg upper-bounds counts
#define F    192               // 3*D features per hop stage
#define OUTC 576               // 9*64 output columns per node
#define SCAN_CHUNK 4096        // elems per scan block (1024 thr x 4)
#define MAXBLK 64
#define TS 71                  // smem tile stride: bank=(7k+d)%32, near conflict-free

// ---- scratch (static device globals; no runtime allocation allowed) ----
__device__ __half  g_xh [(size_t)NMAX * 64];  // x in fp16 (hop-1 gather)
__device__ __half  g_y1h[(size_t)NMAX * F];   // hop-1 result, fp16
__device__ float2  g_s2[NMAX];                // (rsqrt(deg), sqrt(deg)) fp32
__device__ __half2 g_s2h[NMAX];               // (rsqrt(deg), sqrt(deg)) fp16
__device__ int   g_rowptr[NMAX + 1];
__device__ int   g_cursor[NMAX];              // fill cursor; after fill = row end
__device__ int   g_bsum[MAXBLK];              // scan block partials
__device__ int   g_ecol[ESLOTS];              // CSR column indices

// ---------------------------------------------------------------------------
// K1 (merged): blocks [0,nblk) do the per-block local exclusive scan of
// (int)deg (identical to the previous scanA); blocks [nblk, ...) do the
// x->fp16 conversion and per-node scale factors. One kernel boundary before
// scanC covers both. Scan blocks launch first (lowest bids) so the scan's
// critical path isn't delayed by the conversion wave.
// ---------------------------------------------------------------------------
__global__ void scan_init_kernel(const float* __restrict__ x,
                                 const float* __restrict__ deg,
                                 int N, int nblk) {
    if (blockIdx.x >= nblk) {
        // ---- conversion part ----
        int i = (blockIdx.x - nblk) * 1024 + threadIdx.x;
        int total = N * 32;                 // N*64 floats as float2
        if (i < total) {
            float2 v = __ldg(((const float2*)x) + i);
            ((__half2*)g_xh)[i] = __floats2half2_rn(v.x, v.y);
        }
        if (i < N) {
            float d = __ldg(&deg[i]);
            float r = rsqrtf(d);
            float q = d * r;
            g_s2[i]  = make_float2(r, q);
            g_s2h[i] = __floats2half2_rn(r, q);
        }
        return;
    }

    // ---- scan part (identical to previous scanA) ----
    __shared__ int warp_sums[32];
    const int tid = threadIdx.x, lane = tid & 31, wid = tid >> 5;
    int idx = blockIdx.x * SCAN_CHUNK + tid * 4;

    int v0 = (idx     < N) ? (int)__ldg(&deg[idx])     : 0;
    int v1 = (idx + 1 < N) ? (int)__ldg(&deg[idx + 1]) : 0;
    int v2 = (idx + 2 < N) ? (int)__ldg(&deg[idx + 2]) : 0;
    int v3 = (idx + 3 < N) ? (int)__ldg(&deg[idx + 3]) : 0;
    int t = v0 + v1 + v2 + v3;

    int s = t;
    #pragma unroll
    for (int off = 1; off < 32; off <<= 1) {
        int u = __shfl_up_sync(0xFFFFFFFFu, s, off);
        if (lane >= off) s += u;
    }
    if (lane == 31) warp_sums[wid] = s;
    __syncthreads();
    if (wid == 0) {
        int ws = warp_sums[lane];
        int s2 = ws;
        #pragma unroll
        for (int off = 1; off < 32; off <<= 1) {
            int u = __shfl_up_sync(0xFFFFFFFFu, s2, off);
            if (lane >= off) s2 += u;
        }
        warp_sums[lane] = s2 - ws;
    }
    __syncthreads();
    int excl = warp_sums[wid] + (s - t);   // block-local exclusive prefix

    if (idx     < N) g_rowptr[idx]     = excl;
    if (idx + 1 < N) g_rowptr[idx + 1] = excl + v0;
    if (idx + 2 < N) g_rowptr[idx + 2] = excl + v0 + v1;
    if (idx + 3 < N) g_rowptr[idx + 3] = excl + v0 + v1 + v2;
    if (tid == 1023) g_bsum[blockIdx.x] = excl + t;   // block total
}

// ---------------------------------------------------------------------------
// scanC: warp 0 sums predecessors' partials (kernel boundary guarantees
//        visibility), then all threads add the offset and init cursor.
// ---------------------------------------------------------------------------
__global__ void scanC_kernel(int N) {
    __shared__ int s_off;
    const int tid = threadIdx.x, lane = tid & 31;
    if (tid < 32) {                         // warp 0 sums predecessor partials
        int part = (lane < blockIdx.x) ? __ldg(&g_bsum[lane]) : 0;
        #pragma unroll
        for (int off = 16; off > 0; off >>= 1)
            part += __shfl_down_sync(0xFFFFFFFFu, part, off);
        if (lane == 0) s_off = part;
    }
    __syncthreads();
    int off = s_off;
    int idx = blockIdx.x * SCAN_CHUNK + tid * 4;
    #pragma unroll
    for (int k = 0; k < 4; k++) {
        if (idx + k < N) {
            int r = g_rowptr[idx + k] + off;
            g_rowptr[idx + k] = r;
            g_cursor[idx + k] = r;
        }
    }
}

// ---------------------------------------------------------------------------
// K3: scatter edges into CSR buckets, 4 edges/thread for MLP
// ---------------------------------------------------------------------------
__global__ void fill_kernel(const int* __restrict__ row, const int* __restrict__ col, int E) {
    int t = blockIdx.x * blockDim.x + threadIdx.x;
    int e = t * 4;
    if (e + 3 < E) {
        int4 r4 = __ldg((const int4*)(row + e));
        int4 c4 = __ldg((const int4*)(col + e));
        int p0 = atomicAdd(&g_cursor[r4.x], 1);
        int p1 = atomicAdd(&g_cursor[r4.y], 1);
        int p2 = atomicAdd(&g_cursor[r4.z], 1);
        int p3 = atomicAdd(&g_cursor[r4.w], 1);
        g_ecol[p0] = c4.x; g_ecol[p1] = c4.y;
        g_ecol[p2] = c4.z; g_ecol[p3] = c4.w;
    } else {
        for (; e < E; e++) {
            int p = atomicAdd(&g_cursor[row[e]], 1);
            g_ecol[p] = col[e];
        }
    }
}

// ---------------------------------------------------------------------------
// K4: hop-1 SpMM, fp16 HFMA2 accumulation. Warp per node; lane l owns half2
//     column l of each of the 3 feature groups (offsets 0/32/64 half2 units).
// ---------------------------------------------------------------------------
__global__ void spmm1_kernel(const float* __restrict__ deg, int N) {
    int w = (blockIdx.x * blockDim.x + threadIdx.x) >> 5;
    int lane = threadIdx.x & 31;
    if (w >= N) return;
    int s = g_rowptr[w], e = g_cursor[w];   // true end after fill

    __half2 a0 = __float2half2_rn(0.f);
    __half2 a1 = a0, a2 = a0;
    #pragma unroll 4
    for (int p = s; p < e; p++) {
        int j = __ldg(&g_ecol[p]);
        __half2 xv = __ldg(((const __half2*)(g_xh + (size_t)j * 64)) + lane);
        __half2 sh = __ldg(&g_s2h[j]);        // uniform broadcast
        __half2 rr = __low2half2(sh);
        __half2 qq = __high2half2(sh);
        a0 = __hadd2(a0, xv);
        a1 = __hfma2(xv, rr, a1);
        a2 = __hfma2(xv, qq, a2);
    }
    float dr = 1.0f / deg[w];
    float2 f0 = __half22float2(a0);
    float2 f1 = __half22float2(a1);
    float2 f2 = __half22float2(a2);
    __half2* outh = (__half2*)(g_y1h + (size_t)w * F);
    outh[lane]      = __floats2half2_rn(f0.x * dr, f0.y * dr);
    outh[lane + 32] = __floats2half2_rn(f1.x * dr, f1.y * dr);
    outh[lane + 64] = __floats2half2_rn(f2.x * dr, f2.y * dr);
}

// ---------------------------------------------------------------------------
// K5: FUSED hop-2 SpMM + transposed output.
//     Gather: lane l<24 loads uint4 (16B) chunk l of the 384B y1 row ->
//     ONE LDG.128 + 4 HADD2 per edge. Epilogue writes the 9x64 tile with
//     stride TS=71 (bank=(7k+d)%32 — near conflict-free in the transposed
//     read, vs 3-way conflicts at stride 65), then stores coalesced.
// ---------------------------------------------------------------------------
__global__ void spmm2_out_kernel(const float* __restrict__ x,
                                 const float* __restrict__ deg,
                                 float* __restrict__ out, int N) {
    __shared__ float tile[8 * 9 * TS];        // per-warp 9*TS-float tile
    int wid = threadIdx.x >> 5, lane = threadIdx.x & 31;
    int n = blockIdx.x * 8 + wid;
    if (n >= N) return;
    float* t = tile + wid * (9 * TS);
    bool act = lane < 24;

    int s = g_rowptr[n], e = g_cursor[n];
    __half2 acc0 = __float2half2_rn(0.f);
    __half2 acc1 = acc0, acc2 = acc0, acc3 = acc0;
    #pragma unroll 4
    for (int p = s; p < e; p++) {
        int j = __ldg(&g_ecol[p]);
        if (act) {
            uint4 v = __ldg(((const uint4*)(g_y1h + (size_t)j * F)) + lane);
            acc0 = __hadd2(acc0, *(__half2*)&v.x);
            acc1 = __hadd2(acc1, *(__half2*)&v.y);
            acc2 = __hadd2(acc2, *(__half2*)&v.z);
            acc3 = __hadd2(acc3, *(__half2*)&v.w);
        }
    }

    float dr = 1.0f / deg[n];
    float2 sc = g_s2[n];
    if (act) {
        int k = lane >> 3, d0 = (lane & 7) * 8;
        float f = (k == 0) ? 1.0f : ((k == 1) ? sc.x : sc.y);

        // own x slice (exact fp32): 8 floats
        const float* xr = x + (size_t)n * 64 + d0;
        float4 xa = __ldg((const float4*)xr);
        float4 xb = __ldg((const float4*)(xr + 4));

        // own y1 slice (same uint4 mapping)
        uint4 yv = __ldg(((const uint4*)(g_y1h + (size_t)n * F)) + lane);
        float2 y0 = __half22float2(*(__half2*)&yv.x);
        float2 y1 = __half22float2(*(__half2*)&yv.y);
        float2 y2 = __half22float2(*(__half2*)&yv.z);
        float2 y3 = __half22float2(*(__half2*)&yv.w);

        float2 a0 = __half22float2(acc0);
        float2 a1 = __half22float2(acc1);
        float2 a2 = __half22float2(acc2);
        float2 a3 = __half22float2(acc3);

        float x0 = xa.x * f, x1 = xa.y * f, x2 = xa.z * f, x3v = xa.w * f;
        float x4 = xb.x * f, x5 = xb.y * f, x6 = xb.z * f, x7 = xb.w * f;

        float* tk = t + k * TS + d0;               // x3 block
        tk[0] = x0; tk[1] = x1; tk[2] = x2; tk[3] = x3v;
        tk[4] = x4; tk[5] = x5; tk[6] = x6; tk[7] = x7;

        float* t3 = t + (k + 3) * TS + d0;         // y1 block
        t3[0] = y0.x; t3[1] = y0.y; t3[2] = y1.x; t3[3] = y1.y;
        t3[4] = y2.x; t3[5] = y2.y; t3[6] = y3.x; t3[7] = y3.y;

        float* t6 = t + (k + 6) * TS + d0;         // y2 = dr*sum - x3
        t6[0] = a0.x * dr - x0; t6[1] = a0.y * dr - x1;
        t6[2] = a1.x * dr - x2; t6[3] = a1.y * dr - x3v;
        t6[4] = a2.x * dr - x4; t6[5] = a2.y * dr - x5;
        t6[6] = a3.x * dr - x6; t6[7] = a3.y * dr - x7;
    }
    __syncwarp();

    // coalesced store of the transposed row: out[n, d*9+k]
    float* o = out + (size_t)n * OUTC;
    #pragma unroll
    for (int i = 0; i < 18; i++) {
        int r = i * 32 + lane;
        int d = r / 9, k = r - d * 9;
        o[r] = t[k * TS + d];
    }
}

// ---------------------------------------------------------------------------
extern "C" void kernel_launch(void* const* d_in, const int* in_sizes, int n_in,
                              void* d_out, int out_size) {
    const float* x   = (const float*)d_in[0];
    const float* deg = (const float*)d_in[1];
    const int*   row = (const int*)d_in[2];
    const int*   col = (const int*)d_in[3];
    float* out = (float*)d_out;

    int N = in_sizes[1];          // deg has N elements
    int E = in_sizes[2];          // row has E elements
    int nblk = (N + SCAN_CHUNK - 1) / SCAN_CHUNK;      // 25 for N=100000
    int cblk = ((size_t)N * 32 + 1023) / 1024;         // conversion blocks

    scan_init_kernel<<<nblk + cblk, 1024>>>(x, deg, N, nblk);
    scanC_kernel<<<nblk, 1024>>>(N);
    fill_kernel<<<(E / 4 + 255) / 256, 256>>>(row, col, E);
    spmm1_kernel<<<((size_t)N * 32 + 255) / 256, 256>>>(deg, N);
    spmm2_out_kernel<<<(N + 7) / 8, 256>>>(x, deg, out, N);
}